// round 16
// baseline (speedup 1.0000x reference)
#include <cuda_runtime.h>
#include <cuda_fp16.h>
#include <cstdint>

#define TT 128
#define BB 512
#define DD 512
#define OO 10

#define SCL 4096.0f                 // 2^12 operand scale (exact)
#define DSCL 5.9604644775390625e-8f // 2^-24 descale (exact)

// ---------------- device scratch ----------------
static __device__ float     g_Y[TT * BB * DD];       // cur1 pre-BN [t][b][d]
static __device__ __half    g_W1s[2][DD * DD];       // W1*2^12 fp16 limbs, [n][k]
static __device__ __half    g_As[2][TT * BB * DD];   // (mask*data)*2^12 limbs
static __device__ float     g_psum[TT * 8 * DD];     // per-tile column sums
static __device__ float     g_psq[TT * 8 * DD];      // per-tile column sumsqs
static __device__ float     g_mean[TT * DD];
static __device__ float     g_rstd[TT * DD];
static __device__ unsigned  g_spk[TT * BB * (DD / 32)];
static __device__ float     g_W2p[DD][12];           // W2 transposed+padded

// ---------------- helpers ----------------
__device__ __forceinline__ uint32_t smem_u32(const void* p) {
    uint32_t a;
    asm("{ .reg .u64 t; cvta.to.shared.u64 t, %1; cvt.u32.u64 %0, t; }"
        : "=r"(a) : "l"(p));
    return a;
}
#define SWZ128(off) ((off) ^ (((off) >> 3) & 0x70))

__device__ __forceinline__ void cp16(uint32_t dst, const void* src) {
    asm volatile("cp.async.cg.shared.global [%0], [%1], 16;"
                 :: "r"(dst), "l"(src) : "memory");
}
#define CP_COMMIT() asm volatile("cp.async.commit_group;" ::: "memory")
#define CP_WAIT(n)  asm volatile("cp.async.wait_group %0;" :: "n"(n) : "memory")

__device__ __forceinline__ void ldsm_x4(uint32_t* r, uint32_t addr) {
    asm volatile("ldmatrix.sync.aligned.m8n8.x4.shared.b16 {%0,%1,%2,%3}, [%4];"
                 : "=r"(r[0]), "=r"(r[1]), "=r"(r[2]), "=r"(r[3]) : "r"(addr));
}
__device__ __forceinline__ void mma16816(float* c, const uint32_t* a,
                                         uint32_t b0, uint32_t b1) {
    asm volatile(
        "mma.sync.aligned.m16n8k16.row.col.f32.f16.f16.f32 "
        "{%0,%1,%2,%3}, {%4,%5,%6,%7}, {%8,%9}, {%0,%1,%2,%3};"
        : "+f"(c[0]), "+f"(c[1]), "+f"(c[2]), "+f"(c[3])
        : "r"(a[0]), "r"(a[1]), "r"(a[2]), "r"(a[3]), "r"(b0), "r"(b1));
}

// pack two floats -> half2 (RN); unpack halves
__device__ __forceinline__ uint32_t pkh(float lo, float hi) {
    __half2 h = __floats2half2_rn(lo, hi);
    return *(uint32_t*)&h;
}
__device__ __forceinline__ float lo_h(uint32_t v) {
    __half2 h = *(__half2*)&v; return __low2float(h);
}
__device__ __forceinline__ float hi_h(uint32_t v) {
    __half2 h = *(__half2*)&v; return __high2float(h);
}

// ---------------- merged prep: convA everywhere; W1 split in blocks<1024 ----
__global__ void k_prep(const float* __restrict__ data,
                       const float* __restrict__ mask,
                       const float* __restrict__ W1,
                       const float* __restrict__ W2) {
    int id = blockIdx.x * 256 + threadIdx.x;
    {   // A = (mask*data)*2^12 -> 2 fp16 limbs
        int r = id >> 7;                        // row = t*512 + b
        int kq = (id & 127) * 4;
        int t = r >> 9, b = r & 511;
        float4 dv = *(const float4*)(data + ((size_t)b * TT + t) * DD + kq);
        float4 mv = *(const float4*)(mask + ((size_t)t * BB + b) * DD + kq);
        float a0 = dv.x * mv.x * SCL, a1 = dv.y * mv.y * SCL;
        float a2 = dv.z * mv.z * SCL, a3 = dv.w * mv.w * SCL;
        uint32_t h01 = pkh(a0, a1), h23 = pkh(a2, a3);
        float q0 = a0 - lo_h(h01), q1 = a1 - hi_h(h01);
        float q2 = a2 - lo_h(h23), q3 = a3 - hi_h(h23);
        uint32_t m01 = pkh(q0, q1), m23 = pkh(q2, q3);
        size_t o = (size_t)r * DD + kq;
        *(uint2*)(g_As[0] + o) = make_uint2(h01, h23);
        *(uint2*)(g_As[1] + o) = make_uint2(m01, m23);
    }
    if (blockIdx.x < 1024) {   // W1*2^12 -> 2 fp16 limbs
        float a = W1[id] * SCL;
        __half h = __float2half_rn(a);
        float r1 = a - __half2float(h);
        __half m = __float2half_rn(r1);
        g_W1s[0][id] = h; g_W1s[1][id] = m;
    }
    if (blockIdx.x == 0) {     // W2 transpose+pad (bitwise copy)
        #pragma unroll
        for (int it = 0; it < 2; it++) {
            int d = threadIdx.x + it * 256;
            #pragma unroll
            for (int o = 0; o < 10; o++) g_W2p[d][o] = W2[o * DD + d];
            g_W2p[d][10] = 0.f; g_W2p[d][11] = 0.f;
        }
    }
}

// ---------------- FP16x3 split GEMM + fused BN partial sums -----------------
// Mainloop frozen (R11/R14 config). Epilogue additionally reduces column
// sums/sumsqs of the 64x64 Y tile (fixed tree order) into g_psum/g_psq.
#define TILE_L 8192    // 64 rows x 128B per limb
#define BUF_SZ (4 * TILE_L)                  // 32768
#define NSTAGE 3
#define SMEM_DYN (1024 + NSTAGE * BUF_SZ)

__global__ __launch_bounds__(256, 2) void k_gemm() {
    extern __shared__ char smem[];
    const uint32_t s0 = smem_u32(smem);
    const uint32_t base = (s0 + 1023u) & ~1023u;

    const int tid = threadIdx.x;
    const int wid = tid >> 5;
    const int lane = tid & 31;

    const int n0 = blockIdx.x * 64;
    const int r0 = blockIdx.y * 64;

    const int srow = tid >> 2;
    const uint32_t soffb = (uint32_t)((tid & 3) * 32);
    const uint32_t srowb = (uint32_t)srow * 128u;

    const __half* aptr[2];
    const __half* wptr[2];
    #pragma unroll
    for (int s = 0; s < 2; s++) {
        aptr[s] = g_As[s] + (size_t)(r0 + srow) * DD + (soffb >> 1);
        wptr[s] = g_W1s[s] + (size_t)(n0 + srow) * DD + (soffb >> 1);
    }

#define STAGE(kt, buf)                                                          \
    do {                                                                        \
        uint32_t bb = base + (buf) * BUF_SZ;                                    \
        _Pragma("unroll")                                                       \
        for (int s = 0; s < 2; s++) {                                           \
            _Pragma("unroll")                                                   \
            for (int j = 0; j < 2; j++) {                                       \
                uint32_t ob = soffb + j * 16;                                   \
                cp16(bb + s * TILE_L + SWZ128(srowb + ob),                      \
                     aptr[s] + (kt) + j * 8);                                   \
                cp16(bb + (2 + s) * TILE_L + SWZ128(srowb + ob),                \
                     wptr[s] + (kt) + j * 8);                                   \
            }                                                                   \
        }                                                                       \
    } while (0)

    const int wm0 = (wid & 3) * 16;
    const int wn0 = (wid >> 2) * 32;
    const uint32_t a_row = (uint32_t)(wm0 + (lane & 15));
    const uint32_t a_koff = (uint32_t)((lane >> 4) * 8);
    const uint32_t b_row = (uint32_t)(wn0 + ((lane >> 4) << 3) + (lane & 7));
    const uint32_t b_koff = (uint32_t)(((lane >> 3) & 1) * 8);

    float C1[4][4], C2[4][4];
    #pragma unroll
    for (int nf = 0; nf < 4; nf++)
        #pragma unroll
        for (int q = 0; q < 4; q++) { C1[nf][q] = 0.f; C2[nf][q] = 0.f; }

    STAGE(0, 0);
    CP_COMMIT();
    STAGE(64, 1);
    CP_COMMIT();

    #pragma unroll
    for (int c = 0; c < 8; c++) {
        const int buf = c - (c >= 6 ? 6 : (c >= 3 ? 3 : 0));   // c % 3
        if (c < 7) CP_WAIT(1); else CP_WAIT(0);
        __syncthreads();
        if (c + 2 < 8) {
            const int nb = (c + 2) - (c + 2 >= 6 ? 6 : (c + 2 >= 3 ? 3 : 0));
            STAGE((c + 2) * 64, nb);
            CP_COMMIT();
        }

        const uint32_t ab = base + buf * BUF_SZ;
        const uint32_t wb = ab + 2 * TILE_L;
        #pragma unroll
        for (int kk = 0; kk < 4; kk++) {
            uint32_t Af[2][4];
            #pragma unroll
            for (int s = 0; s < 2; s++)
                ldsm_x4(Af[s], ab + s * TILE_L +
                        SWZ128(a_row * 128u + (kk * 16 + a_koff) * 2u));

#define BLOAD(sb, Bf)                                                           \
            _Pragma("unroll")                                                   \
            for (int g = 0; g < 2; g++)                                         \
                ldsm_x4(Bf[g], wb + (sb) * TILE_L +                             \
                        SWZ128((b_row + g * 16) * 128u + (kk * 16 + b_koff) * 2u))
#define PROD(sa, Bf, Cc)                                                        \
            _Pragma("unroll")                                                   \
            for (int g = 0; g < 2; g++) {                                       \
                mma16816(Cc[g * 2],     Af[sa], Bf[g][0], Bf[g][1]);            \
                mma16816(Cc[g * 2 + 1], Af[sa], Bf[g][2], Bf[g][3]);            \
            }
            {   // b1: a1b1 -> C1, a2b1 -> C2
                uint32_t Bf[2][4];
                BLOAD(0, Bf);
                PROD(0, Bf, C1); PROD(1, Bf, C2);
            }
            {   // b2: a1b2 -> C2
                uint32_t Bf[2][4];
                BLOAD(1, Bf);
                PROD(0, Bf, C2);
            }
#undef PROD
#undef BLOAD
        }
    }

    // ---- epilogue: write Y; reduce column sums/sumsqs (fixed tree order) ----
    float colsum[8], colsq[8];
    {
        int rbase = r0 + wm0 + (lane >> 2);
        #pragma unroll
        for (int nf = 0; nf < 4; nf++) {
            int col = n0 + wn0 + nf * 8 + (lane & 3) * 2;
            float y0 = (C1[nf][0] + C2[nf][0]) * DSCL;
            float y1 = (C1[nf][1] + C2[nf][1]) * DSCL;
            float y2 = (C1[nf][2] + C2[nf][2]) * DSCL;
            float y3 = (C1[nf][3] + C2[nf][3]) * DSCL;
            *(float2*)(g_Y + (size_t)rbase * DD + col) = make_float2(y0, y1);
            *(float2*)(g_Y + (size_t)(rbase + 8) * DD + col) = make_float2(y2, y3);
            colsum[nf * 2 + 0] = y0 + y2;
            colsum[nf * 2 + 1] = y1 + y3;
            colsq[nf * 2 + 0] = y0 * y0 + y2 * y2;
            colsq[nf * 2 + 1] = y1 * y1 + y3 * y3;
        }
    }
    #pragma unroll
    for (int off = 4; off <= 16; off <<= 1)
        #pragma unroll
        for (int i = 0; i < 8; i++) {
            colsum[i] += __shfl_xor_sync(0xffffffffu, colsum[i], off);
            colsq[i]  += __shfl_xor_sync(0xffffffffu, colsq[i], off);
        }
    float* sred = (float*)(smem + (base - s0));   // staging smem is dead now
    __syncthreads();
    if (lane < 4) {
        #pragma unroll
        for (int nf = 0; nf < 4; nf++)
            #pragma unroll
            for (int j = 0; j < 2; j++) {
                int cl = wn0 + nf * 8 + lane * 2 + j;          // 0..63
                sred[(wid & 3) * 128 + cl * 2 + 0] = colsum[nf * 2 + j];
                sred[(wid & 3) * 128 + cl * 2 + 1] = colsq[nf * 2 + j];
            }
    }
    __syncthreads();
    if (tid < 64) {
        float s = sred[0 * 128 + tid * 2] + sred[1 * 128 + tid * 2]
                + sred[2 * 128 + tid * 2] + sred[3 * 128 + tid * 2];
        float q = sred[0 * 128 + tid * 2 + 1] + sred[1 * 128 + tid * 2 + 1]
                + sred[2 * 128 + tid * 2 + 1] + sred[3 * 128 + tid * 2 + 1];
        g_psum[(size_t)blockIdx.y * DD + n0 + tid] = s;   // blockIdx.y = t*8+bt
        g_psq[(size_t)blockIdx.y * DD + n0 + tid] = q;
    }
}

// ---------------- BN stats from partials (4MB instead of 128MB) -------------
__global__ __launch_bounds__(256) void k_stats() {
    int idx = blockIdx.x * 256 + threadIdx.x;  // t*512 + d
    int t = idx >> 9, d = idx & 511;
    float s = 0.f, q = 0.f;
    #pragma unroll
    for (int bt = 0; bt < 8; bt++) {
        s += g_psum[(size_t)(t * 8 + bt) * DD + d];
        q += g_psq[(size_t)(t * 8 + bt) * DD + d];
    }
    float mean = s * (1.0f / BB);
    float var = q * (1.0f / BB) - mean * mean;
    g_mean[idx] = mean;
    g_rstd[idx] = (float)(1.0 / sqrt((double)(var + 1e-5f)));
}

// ---------------- layer-1 membrane scan: 2 chains/thread (launch #4) --------
__global__ void k_scan1(const float* __restrict__ gamma,
                        const float* __restrict__ beta) {
    int id = blockIdx.x * 256 + threadIdx.x;  // b0*512 + d, b0 in [0,256)
    int b0 = id >> 9, d = id & 511;
    int lane = threadIdx.x & 31;
    float g = gamma[d], be = beta[d];
    float mem0 = 0.f, spk0 = 0.f, mem1 = 0.f, spk1 = 0.f;
    const float* yp0 = g_Y + (size_t)b0 * DD + d;
    const float* yp1 = yp0 + (size_t)256 * DD;
    unsigned* sp0 = g_spk + (size_t)b0 * 16 + (d >> 5);
    unsigned* sp1 = sp0 + 256 * 16;
    for (int t0 = 0; t0 < TT; t0 += 8) {
        float y0[8], y1[8], mn[8], rs[8];
        #pragma unroll
        for (int i = 0; i < 8; i++) {
            y0[i] = yp0[(size_t)(t0 + i) * BB * DD];
            y1[i] = yp1[(size_t)(t0 + i) * BB * DD];
            mn[i] = g_mean[(t0 + i) * DD + d];
            rs[i] = g_rstd[(t0 + i) * DD + d];
        }
        #pragma unroll
        for (int i = 0; i < 8; i++) {
            float cur0 = g * (y0[i] - mn[i]) * rs[i] + be;
            mem0 = 0.5f * mem0 + cur0 - spk0;
            spk0 = (mem0 - 1.0f) > 0.f ? 1.0f : 0.0f;
            float cur1 = g * (y1[i] - mn[i]) * rs[i] + be;
            mem1 = 0.5f * mem1 + cur1 - spk1;
            spk1 = (mem1 - 1.0f) > 0.f ? 1.0f : 0.0f;
            unsigned bal0 = __ballot_sync(0xffffffffu, spk0 != 0.f);
            unsigned bal1 = __ballot_sync(0xffffffffu, spk1 != 0.f);
            if (lane == 0) {
                sp0[(size_t)(t0 + i) * BB * 16] = bal0;
                sp1[(size_t)(t0 + i) * BB * 16] = bal1;
            }
        }
    }
}

// ---------------- fused layer2 + scan2: one block per batch b ---------------
__global__ __launch_bounds__(256) void k_l2s2(const float* __restrict__ b2,
                                              float* __restrict__ out) {
    __shared__ float cur2s[TT][10];
    int b = blockIdx.x;
    int wid = threadIdx.x >> 5, lane = threadIdx.x & 31;

    for (int t = wid; t < TT; t += 8) {
        const unsigned* sp = g_spk + ((size_t)t * BB + b) * 16;
        float acc[10];
        #pragma unroll
        for (int o = 0; o < 10; o++) acc[o] = 0.f;
        #pragma unroll
        for (int j = 0; j < 16; j++) {
            unsigned w = sp[j];
            float s = ((w >> lane) & 1u) ? 1.0f : 0.0f;
            int d = j * 32 + lane;
            const float4* wp = (const float4*)g_W2p[d];
            float4 v0 = wp[0], v1 = wp[1], v2 = wp[2];
            acc[0] += s * v0.x; acc[1] += s * v0.y; acc[2] += s * v0.z; acc[3] += s * v0.w;
            acc[4] += s * v1.x; acc[5] += s * v1.y; acc[6] += s * v1.z; acc[7] += s * v1.w;
            acc[8] += s * v2.x; acc[9] += s * v2.y;
        }
        #pragma unroll
        for (int o = 0; o < 10; o++) {
            #pragma unroll
            for (int off = 16; off; off >>= 1)
                acc[o] += __shfl_xor_sync(0xffffffffu, acc[o], off);
        }
        if (lane == 0) {
            #pragma unroll
            for (int o = 0; o < 10; o++) cur2s[t][o] = acc[o] + b2[o];
        }
    }
    __syncthreads();

    if (threadIdx.x < 10) {
        int o = threadIdx.x;
        float mem = 0.f, spk = 0.f;
        for (int t = 0; t < TT; t++) {
            float c = cur2s[t][o];
            mem = 0.5f * mem + c - spk;
            spk = (mem - 1.0f) > 0.f ? 1.0f : 0.0f;
            out[((size_t)t * BB + b) * 10 + o] = spk;
        }
    }
}

extern "C" void kernel_launch(void* const* d_in, const int* in_sizes, int n_in,
                              void* d_out, int out_size) {
    const float* data  = (const float*)d_in[0];  // [B,T,D]
    const float* mask  = (const float*)d_in[1];  // [T,B,D]
    const float* W1    = (const float*)d_in[2];  // [D,D]
    // d_in[3] = b1: cancels exactly under BatchNorm mean subtraction
    const float* gamma = (const float*)d_in[4];
    const float* beta  = (const float*)d_in[5];
    const float* W2    = (const float*)d_in[6];  // [O,D]
    const float* b2    = (const float*)d_in[7];
    float* out = (float*)d_out;                  // [T,B,O]

    cudaFuncSetAttribute(k_gemm, cudaFuncAttributeMaxDynamicSharedMemorySize, SMEM_DYN);

    k_prep<<<32768, 256>>>(data, mask, W1, W2);
    k_gemm<<<dim3(8, 1024), 256, SMEM_DYN>>>();
    k_stats<<<256, 256>>>();
    k_scan1<<<512, 256>>>(gamma, beta);     // launch #4: ncu capture slot
    k_l2s2<<<512, 256>>>(b2, out);
}

// round 17
// speedup vs baseline: 1.0281x; 1.0281x over previous
#include <cuda_runtime.h>
#include <cuda_fp16.h>
#include <cstdint>

#define TT 128
#define BB 512
#define DD 512
#define OO 10

#define SCL 4096.0f                 // 2^12 operand scale (exact)
#define DSCL 5.9604644775390625e-8f // 2^-24 descale (exact)

// ---------------- device scratch ----------------
static __device__ float     g_Y[TT * BB * DD];       // cur1 pre-BN [t][b][d]
static __device__ __half    g_W1s[2][DD * DD];       // W1*2^12 fp16 limbs, [n][k]
static __device__ __half    g_As[2][TT * BB * DD];   // (mask*data)*2^12 limbs
static __device__ float2    g_ms[TT * DD];           // {s1 = g*rstd, s0 = be - mean*s1}
static __device__ unsigned  g_spk[TT * BB * (DD / 32)];
static __device__ float     g_W2p[DD][12];           // W2 transposed+padded

// ---------------- helpers ----------------
__device__ __forceinline__ uint32_t smem_u32(const void* p) {
    uint32_t a;
    asm("{ .reg .u64 t; cvta.to.shared.u64 t, %1; cvt.u32.u64 %0, t; }"
        : "=r"(a) : "l"(p));
    return a;
}
#define SWZ128(off) ((off) ^ (((off) >> 3) & 0x70))

__device__ __forceinline__ void cp16(uint32_t dst, const void* src) {
    asm volatile("cp.async.cg.shared.global [%0], [%1], 16;"
                 :: "r"(dst), "l"(src) : "memory");
}
#define CP_COMMIT() asm volatile("cp.async.commit_group;" ::: "memory")
#define CP_WAIT(n)  asm volatile("cp.async.wait_group %0;" :: "n"(n) : "memory")

__device__ __forceinline__ void ldsm_x4(uint32_t* r, uint32_t addr) {
    asm volatile("ldmatrix.sync.aligned.m8n8.x4.shared.b16 {%0,%1,%2,%3}, [%4];"
                 : "=r"(r[0]), "=r"(r[1]), "=r"(r[2]), "=r"(r[3]) : "r"(addr));
}
__device__ __forceinline__ void mma16816(float* c, const uint32_t* a,
                                         uint32_t b0, uint32_t b1) {
    asm volatile(
        "mma.sync.aligned.m16n8k16.row.col.f32.f16.f16.f32 "
        "{%0,%1,%2,%3}, {%4,%5,%6,%7}, {%8,%9}, {%0,%1,%2,%3};"
        : "+f"(c[0]), "+f"(c[1]), "+f"(c[2]), "+f"(c[3])
        : "r"(a[0]), "r"(a[1]), "r"(a[2]), "r"(a[3]), "r"(b0), "r"(b1));
}

// pack two floats -> half2 (RN); unpack halves
__device__ __forceinline__ uint32_t pkh(float lo, float hi) {
    __half2 h = __floats2half2_rn(lo, hi);
    return *(uint32_t*)&h;
}
__device__ __forceinline__ float lo_h(uint32_t v) {
    __half2 h = *(__half2*)&v; return __low2float(h);
}
__device__ __forceinline__ float hi_h(uint32_t v) {
    __half2 h = *(__half2*)&v; return __high2float(h);
}

// ---------------- merged prep: convA everywhere; W1 split in blocks<1024 ----
__global__ void k_prep(const float* __restrict__ data,
                       const float* __restrict__ mask,
                       const float* __restrict__ W1,
                       const float* __restrict__ W2) {
    int id = blockIdx.x * 256 + threadIdx.x;
    {   // A = (mask*data)*2^12 -> 2 fp16 limbs
        int r = id >> 7;                        // row = t*512 + b
        int kq = (id & 127) * 4;
        int t = r >> 9, b = r & 511;
        float4 dv = *(const float4*)(data + ((size_t)b * TT + t) * DD + kq);
        float4 mv = *(const float4*)(mask + ((size_t)t * BB + b) * DD + kq);
        float a0 = dv.x * mv.x * SCL, a1 = dv.y * mv.y * SCL;
        float a2 = dv.z * mv.z * SCL, a3 = dv.w * mv.w * SCL;
        uint32_t h01 = pkh(a0, a1), h23 = pkh(a2, a3);
        float q0 = a0 - lo_h(h01), q1 = a1 - hi_h(h01);
        float q2 = a2 - lo_h(h23), q3 = a3 - hi_h(h23);
        uint32_t m01 = pkh(q0, q1), m23 = pkh(q2, q3);
        size_t o = (size_t)r * DD + kq;
        *(uint2*)(g_As[0] + o) = make_uint2(h01, h23);
        *(uint2*)(g_As[1] + o) = make_uint2(m01, m23);
    }
    if (blockIdx.x < 1024) {   // W1*2^12 -> 2 fp16 limbs
        float a = W1[id] * SCL;
        __half h = __float2half_rn(a);
        float r1 = a - __half2float(h);
        __half m = __float2half_rn(r1);
        g_W1s[0][id] = h; g_W1s[1][id] = m;
    }
    if (blockIdx.x == 0) {     // W2 transpose+pad (bitwise copy)
        #pragma unroll
        for (int it = 0; it < 2; it++) {
            int d = threadIdx.x + it * 256;
            #pragma unroll
            for (int o = 0; o < 10; o++) g_W2p[d][o] = W2[o * DD + d];
            g_W2p[d][10] = 0.f; g_W2p[d][11] = 0.f;
        }
    }
}

// ---------------- FP16x3 split GEMM: CTA 64x64, warp 16x32, 3-stage ---------
// (Frozen R11/R14/R15 configuration: 263us measured, rel_err 0.0.)
#define TILE_L 8192    // 64 rows x 128B per limb
#define BUF_SZ (4 * TILE_L)                  // 32768
#define NSTAGE 3
#define SMEM_DYN (1024 + NSTAGE * BUF_SZ)

__global__ __launch_bounds__(256, 2) void k_gemm() {
    extern __shared__ char smem[];
    const uint32_t s0 = smem_u32(smem);
    const uint32_t base = (s0 + 1023u) & ~1023u;

    const int tid = threadIdx.x;
    const int wid = tid >> 5;
    const int lane = tid & 31;

    const int n0 = blockIdx.x * 64;
    const int r0 = blockIdx.y * 64;

    const int srow = tid >> 2;
    const uint32_t soffb = (uint32_t)((tid & 3) * 32);
    const uint32_t srowb = (uint32_t)srow * 128u;

    const __half* aptr[2];
    const __half* wptr[2];
    #pragma unroll
    for (int s = 0; s < 2; s++) {
        aptr[s] = g_As[s] + (size_t)(r0 + srow) * DD + (soffb >> 1);
        wptr[s] = g_W1s[s] + (size_t)(n0 + srow) * DD + (soffb >> 1);
    }

#define STAGE(kt, buf)                                                          \
    do {                                                                        \
        uint32_t bb = base + (buf) * BUF_SZ;                                    \
        _Pragma("unroll")                                                       \
        for (int s = 0; s < 2; s++) {                                           \
            _Pragma("unroll")                                                   \
            for (int j = 0; j < 2; j++) {                                       \
                uint32_t ob = soffb + j * 16;                                   \
                cp16(bb + s * TILE_L + SWZ128(srowb + ob),                      \
                     aptr[s] + (kt) + j * 8);                                   \
                cp16(bb + (2 + s) * TILE_L + SWZ128(srowb + ob),                \
                     wptr[s] + (kt) + j * 8);                                   \
            }                                                                   \
        }                                                                       \
    } while (0)

    const int wm0 = (wid & 3) * 16;
    const int wn0 = (wid >> 2) * 32;
    const uint32_t a_row = (uint32_t)(wm0 + (lane & 15));
    const uint32_t a_koff = (uint32_t)((lane >> 4) * 8);
    const uint32_t b_row = (uint32_t)(wn0 + ((lane >> 4) << 3) + (lane & 7));
    const uint32_t b_koff = (uint32_t)(((lane >> 3) & 1) * 8);

    float C1[4][4], C2[4][4];
    #pragma unroll
    for (int nf = 0; nf < 4; nf++)
        #pragma unroll
        for (int q = 0; q < 4; q++) { C1[nf][q] = 0.f; C2[nf][q] = 0.f; }

    STAGE(0, 0);
    CP_COMMIT();
    STAGE(64, 1);
    CP_COMMIT();

    #pragma unroll
    for (int c = 0; c < 8; c++) {
        const int buf = c - (c >= 6 ? 6 : (c >= 3 ? 3 : 0));   // c % 3
        if (c < 7) CP_WAIT(1); else CP_WAIT(0);
        __syncthreads();
        if (c + 2 < 8) {
            const int nb = (c + 2) - (c + 2 >= 6 ? 6 : (c + 2 >= 3 ? 3 : 0));
            STAGE((c + 2) * 64, nb);
            CP_COMMIT();
        }

        const uint32_t ab = base + buf * BUF_SZ;
        const uint32_t wb = ab + 2 * TILE_L;
        #pragma unroll
        for (int kk = 0; kk < 4; kk++) {
            uint32_t Af[2][4];
            #pragma unroll
            for (int s = 0; s < 2; s++)
                ldsm_x4(Af[s], ab + s * TILE_L +
                        SWZ128(a_row * 128u + (kk * 16 + a_koff) * 2u));

#define BLOAD(sb, Bf)                                                           \
            _Pragma("unroll")                                                   \
            for (int g = 0; g < 2; g++)                                         \
                ldsm_x4(Bf[g], wb + (sb) * TILE_L +                             \
                        SWZ128((b_row + g * 16) * 128u + (kk * 16 + b_koff) * 2u))
#define PROD(sa, Bf, Cc)                                                        \
            _Pragma("unroll")                                                   \
            for (int g = 0; g < 2; g++) {                                       \
                mma16816(Cc[g * 2],     Af[sa], Bf[g][0], Bf[g][1]);            \
                mma16816(Cc[g * 2 + 1], Af[sa], Bf[g][2], Bf[g][3]);            \
            }
            {   // b1: a1b1 -> C1, a2b1 -> C2
                uint32_t Bf[2][4];
                BLOAD(0, Bf);
                PROD(0, Bf, C1); PROD(1, Bf, C2);
            }
            {   // b2: a1b2 -> C2
                uint32_t Bf[2][4];
                BLOAD(1, Bf);
                PROD(0, Bf, C2);
            }
#undef PROD
#undef BLOAD
        }
    }

    {
        int rbase = r0 + wm0 + (lane >> 2);
        #pragma unroll
        for (int nf = 0; nf < 4; nf++) {
            int col = n0 + wn0 + nf * 8 + (lane & 3) * 2;
            *(float2*)(g_Y + (size_t)rbase * DD + col) =
                make_float2((C1[nf][0] + C2[nf][0]) * DSCL,
                            (C1[nf][1] + C2[nf][1]) * DSCL);
            *(float2*)(g_Y + (size_t)(rbase + 8) * DD + col) =
                make_float2((C1[nf][2] + C2[nf][2]) * DSCL,
                            (C1[nf][3] + C2[nf][3]) * DSCL);
        }
    }
}

// ---------------- BN stats: one pass + folded affine coefficients -----------
// mean/var/rsqrt identical to the validated R15 form; then fold gamma/beta:
// s1 = g*rstd, s0 = be - mean*s1, so scan1 does cur = fma(y, s1, s0).
__global__ __launch_bounds__(256) void k_stats(const float* __restrict__ gamma,
                                               const float* __restrict__ beta) {
    int t = blockIdx.x >> 1;
    int d = (blockIdx.x & 1) * 256 + threadIdx.x;
    const float* col = g_Y + (size_t)t * BB * DD + d;
    float s = 0.f, sq = 0.f;
    for (int b = 0; b < BB; b++) {
        float x = col[(size_t)b * DD];
        s += x;
        sq += x * x;
    }
    float mean = s * (1.0f / BB);
    float var = sq * (1.0f / BB) - mean * mean;
    float rstd = (float)(1.0 / sqrt((double)(var + 1e-5f)));
    float s1 = gamma[d] * rstd;
    float s0 = fmaf(-mean, s1, beta[d]);
    g_ms[t * DD + d] = make_float2(s1, s0);
}

// ---------------- layer-1 membrane scan (launch #4: ncu slot) ---------------
__global__ void k_scan1() {
    int id = blockIdx.x * 256 + threadIdx.x;  // b*512 + d
    int b = id >> 9, d = id & 511;
    int lane = threadIdx.x & 31;
    float mem = 0.f, spk = 0.f;
    const float* yp = g_Y + (size_t)b * DD + d;
    unsigned* sp = g_spk + (size_t)b * 16 + (d >> 5);
    for (int t0 = 0; t0 < TT; t0 += 8) {
        float y[8];
        float2 ms[8];
        #pragma unroll
        for (int i = 0; i < 8; i++) {
            y[i]  = yp[(size_t)(t0 + i) * BB * DD];
            ms[i] = g_ms[(t0 + i) * DD + d];
        }
        #pragma unroll
        for (int i = 0; i < 8; i++) {
            float cur = fmaf(y[i], ms[i].x, ms[i].y);
            mem = 0.5f * mem + cur - spk;
            spk = (mem - 1.0f) > 0.f ? 1.0f : 0.0f;
            unsigned bal = __ballot_sync(0xffffffffu, spk != 0.f);
            if (lane == 0) sp[(size_t)(t0 + i) * BB * 16] = bal;
        }
    }
}

// ---------------- fused layer2 + scan2: one block per batch b ---------------
__global__ __launch_bounds__(256) void k_l2s2(const float* __restrict__ b2,
                                              float* __restrict__ out) {
    __shared__ float cur2s[TT][10];
    int b = blockIdx.x;
    int wid = threadIdx.x >> 5, lane = threadIdx.x & 31;

    for (int t = wid; t < TT; t += 8) {
        const unsigned* sp = g_spk + ((size_t)t * BB + b) * 16;
        float acc[10];
        #pragma unroll
        for (int o = 0; o < 10; o++) acc[o] = 0.f;
        #pragma unroll
        for (int j = 0; j < 16; j++) {
            unsigned w = sp[j];
            float s = ((w >> lane) & 1u) ? 1.0f : 0.0f;
            int d = j * 32 + lane;
            const float4* wp = (const float4*)g_W2p[d];
            float4 v0 = wp[0], v1 = wp[1], v2 = wp[2];
            acc[0] += s * v0.x; acc[1] += s * v0.y; acc[2] += s * v0.z; acc[3] += s * v0.w;
            acc[4] += s * v1.x; acc[5] += s * v1.y; acc[6] += s * v1.z; acc[7] += s * v1.w;
            acc[8] += s * v2.x; acc[9] += s * v2.y;
        }
        #pragma unroll
        for (int o = 0; o < 10; o++) {
            #pragma unroll
            for (int off = 16; off; off >>= 1)
                acc[o] += __shfl_xor_sync(0xffffffffu, acc[o], off);
        }
        if (lane == 0) {
            #pragma unroll
            for (int o = 0; o < 10; o++) cur2s[t][o] = acc[o] + b2[o];
        }
    }
    __syncthreads();

    if (threadIdx.x < 10) {
        int o = threadIdx.x;
        float mem = 0.f, spk = 0.f;
        for (int t = 0; t < TT; t++) {
            float c = cur2s[t][o];
            mem = 0.5f * mem + c - spk;
            spk = (mem - 1.0f) > 0.f ? 1.0f : 0.0f;
            out[((size_t)t * BB + b) * 10 + o] = spk;
        }
    }
}

extern "C" void kernel_launch(void* const* d_in, const int* in_sizes, int n_in,
                              void* d_out, int out_size) {
    const float* data  = (const float*)d_in[0];  // [B,T,D]
    const float* mask  = (const float*)d_in[1];  // [T,B,D]
    const float* W1    = (const float*)d_in[2];  // [D,D]
    // d_in[3] = b1: cancels exactly under BatchNorm mean subtraction
    const float* gamma = (const float*)d_in[4];
    const float* beta  = (const float*)d_in[5];
    const float* W2    = (const float*)d_in[6];  // [O,D]
    const float* b2    = (const float*)d_in[7];
    float* out = (float*)d_out;                  // [T,B,O]

    cudaFuncSetAttribute(k_gemm, cudaFuncAttributeMaxDynamicSharedMemorySize, SMEM_DYN);

    k_prep<<<32768, 256>>>(data, mask, W1, W2);
    k_gemm<<<dim3(8, 1024), 256, SMEM_DYN>>>();
    k_stats<<<256, 256>>>(gamma, beta);
    k_scan1<<<1024, 256>>>();               // launch #4: ncu capture slot
    k_l2s2<<<512, 256>>>(b2, out);
}